// round 12
// baseline (speedup 1.0000x reference)
#include <cuda_runtime.h>
#include <math.h>
#include <stdint.h>

namespace {
constexpr int QB = 2, QL = 2048, QD = 512, QH = 8, QDh = 64;
constexpr int QBH = QB * QH;
constexpr size_t RIOFF = (size_t)QBH * QL * QDh;
constexpr size_t QSZ   = 2 * RIOFF;
constexpr size_t SSZ   = (size_t)QBH * QL * QL;
}

__device__ uint32_t g_Qh[QSZ], g_Ql[QSZ];
__device__ uint32_t g_Kh[QSZ], g_Kl[QSZ];
__device__ uint32_t g_Vh[QSZ], g_Vl[QSZ];
__device__ float g_Sr[SSZ], g_Si[SSZ];
__device__ float g_m[QBH * QL], g_il[QBH * QL];
__device__ float g_Or[(size_t)QB * QL * QD], g_Oi[(size_t)QB * QL * QD];

__device__ __forceinline__ uint32_t tf32h(float x) {
    uint32_t u; asm("cvt.rna.tf32.f32 %0, %1;" : "=r"(u) : "f"(x)); return u;
}
__device__ __forceinline__ void f2tf(float x, uint32_t& h, uint32_t& l) {
    h = tf32h(x);
    l = tf32h(x - __uint_as_float(h));
}
__device__ __forceinline__ void mma8(float c[4], const uint32_t a[4],
                                     uint32_t b0, uint32_t b1) {
    asm volatile(
        "mma.sync.aligned.m16n8k8.row.col.f32.tf32.tf32.f32 "
        "{%0,%1,%2,%3},{%4,%5,%6,%7},{%8,%9},{%0,%1,%2,%3};"
        : "+f"(c[0]), "+f"(c[1]), "+f"(c[2]), "+f"(c[3])
        : "r"(a[0]), "r"(a[1]), "r"(a[2]), "r"(a[3]), "r"(b0), "r"(b1));
}

// exp(x) for x <= 0, FMA-pipe only (no MUFU). ~1e-7 relative accuracy.
__device__ __forceinline__ float exp_neg_fast(float x) {
    const float LOG2E = 1.4426950408889634f;
    float t = x * LOG2E;
    float fl = floorf(t);
    float r = t - fl;
    float y = r * 0.6931471805599453f;
    float p = 2.4801587301587301e-5f;
    p = fmaf(p, y, 1.9841269841269841e-4f);
    p = fmaf(p, y, 1.3888888888888889e-3f);
    p = fmaf(p, y, 8.3333333333333333e-3f);
    p = fmaf(p, y, 4.1666666666666664e-2f);
    p = fmaf(p, y, 1.6666666666666666e-1f);
    p = fmaf(p, y, 5.0e-1f);
    p = fmaf(p, y, 1.0f);
    p = fmaf(p, y, 1.0f);
    int ni = (int)fl;
    ni = (ni < -127) ? -127 : ni;
    float sc = __int_as_float((uint32_t)(ni + 127) << 23);
    return p * sc;
}

__device__ __forceinline__ float rsqrt_fast(float x) {
    float y = __int_as_float(0x5f375a86u - (__float_as_uint(x) >> 1));
    y = y * fmaf(-0.5f * x, y * y, 1.5f);
    y = y * fmaf(-0.5f * x, y * y, 1.5f);
    return y;
}

// ---------------------------------------------------------------------------
// Projections on tensor cores (split-tf32, 3 passes).
// Block 128x128, 8 warps = 4 wq x 2 wn, warp tile 32x64.
// MODE 0: scatter-store to tf32 hi/lo planes of Q/K/V (sel).
// MODE 1: X = g_Or/g_Oi; row-major float out.
// ---------------------------------------------------------------------------
template <int MODE>
__global__ __launch_bounds__(256) void proj_mma(
    const float* __restrict__ X0, const float* __restrict__ X1,
    const float* __restrict__ Wt, const float* __restrict__ bias,
    float* __restrict__ Yext, int sel)
{
    __shared__ uint32_t sA[2][16 * 132];
    __shared__ uint32_t sW[2][16 * 132];

    const int tid = threadIdx.x;
    const int r0 = blockIdx.y * 128;
    const int c0 = blockIdx.x * 128;

    const float* X;
    int rbase = r0;
    if (MODE == 0) {
        if (r0 >= 4096) { X = X1; rbase = r0 - 4096; }
        else            { X = X0; }
    } else {
        X = sel ? g_Oi : g_Or;
    }

    const int warp = tid >> 5, lane = tid & 31;
    const int wq = warp >> 1, wn = warp & 1;
    const int g = lane >> 2, t = lane & 3;

    const int lr = tid >> 1;
    const int lc0 = (tid & 1) << 2;

    float C[2][8][4];
    #pragma unroll
    for (int m = 0; m < 2; m++)
        #pragma unroll
        for (int i = 0; i < 8; i++)
            #pragma unroll
            for (int j = 0; j < 4; j++) C[m][i][j] = 0.f;

    for (int k0 = 0; k0 < 512; k0 += 16) {
        __syncthreads();
        #pragma unroll
        for (int it = 0; it < 2; ++it) {
            const int kk = lc0 + it * 8;
            float4 a = *(const float4*)(X  + (size_t)(rbase + lr) * 512 + k0 + kk);
            float4 w = *(const float4*)(Wt + (size_t)(c0 + lr) * 512 + k0 + kk);
            uint32_t h, l;
            f2tf(a.x, h, l); sA[0][(kk + 0) * 132 + lr] = h; sA[1][(kk + 0) * 132 + lr] = l;
            f2tf(a.y, h, l); sA[0][(kk + 1) * 132 + lr] = h; sA[1][(kk + 1) * 132 + lr] = l;
            f2tf(a.z, h, l); sA[0][(kk + 2) * 132 + lr] = h; sA[1][(kk + 2) * 132 + lr] = l;
            f2tf(a.w, h, l); sA[0][(kk + 3) * 132 + lr] = h; sA[1][(kk + 3) * 132 + lr] = l;
            f2tf(w.x, h, l); sW[0][(kk + 0) * 132 + lr] = h; sW[1][(kk + 0) * 132 + lr] = l;
            f2tf(w.y, h, l); sW[0][(kk + 1) * 132 + lr] = h; sW[1][(kk + 1) * 132 + lr] = l;
            f2tf(w.z, h, l); sW[0][(kk + 2) * 132 + lr] = h; sW[1][(kk + 2) * 132 + lr] = l;
            f2tf(w.w, h, l); sW[0][(kk + 3) * 132 + lr] = h; sW[1][(kk + 3) * 132 + lr] = l;
        }
        __syncthreads();

        #pragma unroll
        for (int ks = 0; ks < 2; ++ks) {
            const int kd = ks * 8 + t;
            uint32_t ah[2][4], al[2][4];
            #pragma unroll
            for (int m = 0; m < 2; m++) {
                const int row = wq * 32 + m * 16 + g;
                ah[m][0] = sA[0][kd * 132 + row];
                ah[m][1] = sA[0][kd * 132 + row + 8];
                ah[m][2] = sA[0][(kd + 4) * 132 + row];
                ah[m][3] = sA[0][(kd + 4) * 132 + row + 8];
                al[m][0] = sA[1][kd * 132 + row];
                al[m][1] = sA[1][kd * 132 + row + 8];
                al[m][2] = sA[1][(kd + 4) * 132 + row];
                al[m][3] = sA[1][(kd + 4) * 132 + row + 8];
            }
            #pragma unroll
            for (int nt = 0; nt < 8; ++nt) {
                const int cb = wn * 64 + nt * 8 + g;
                uint32_t bh0 = sW[0][kd * 132 + cb];
                uint32_t bh1 = sW[0][(kd + 4) * 132 + cb];
                uint32_t bl0 = sW[1][kd * 132 + cb];
                uint32_t bl1 = sW[1][(kd + 4) * 132 + cb];
                #pragma unroll
                for (int m = 0; m < 2; m++) {
                    mma8(C[m][nt], ah[m], bh0, bh1);
                    mma8(C[m][nt], ah[m], bl0, bl1);
                    mma8(C[m][nt], al[m], bh0, bh1);
                }
            }
        }
    }

    #pragma unroll
    for (int m = 0; m < 2; m++) {
        const int row0 = r0 + wq * 32 + m * 16 + g;
        #pragma unroll
        for (int nt = 0; nt < 8; ++nt) {
            const int col = c0 + wn * 64 + nt * 8 + 2 * t;
            const float b0 = bias[col], b1 = bias[col + 1];
            float v00 = C[m][nt][0] + b0, v01 = C[m][nt][1] + b1;
            float v10 = C[m][nt][2] + b0, v11 = C[m][nt][3] + b1;
            if (MODE == 0) {
                uint32_t* dH = (sel == 0) ? g_Qh : (sel == 1) ? g_Kh : g_Vh;
                uint32_t* dL = (sel == 0) ? g_Ql : (sel == 1) ? g_Kl : g_Vl;
                #pragma unroll
                for (int e = 0; e < 4; ++e) {
                    const int r = row0 + (e >> 1) * 8;
                    const int c = col + (e & 1);
                    const float v = (e == 0) ? v00 : (e == 1) ? v01 : (e == 2) ? v10 : v11;
                    const int ri = r >> 12;
                    const int bl = r & 4095;
                    const int bb = bl >> 11;
                    const int l  = bl & 2047;
                    const int h  = c >> 6;
                    const int dh = c & 63;
                    size_t idx = ((((size_t)ri * QB + bb) * QH + h) * QL + l) * QDh + dh;
                    uint32_t hh, ll; f2tf(v, hh, ll);
                    dH[idx] = hh; dL[idx] = ll;
                }
            } else {
                *(float2*)(Yext + (size_t)row0 * 512 + col) = make_float2(v00, v01);
                *(float2*)(Yext + (size_t)(row0 + 8) * 512 + col) = make_float2(v10, v11);
            }
        }
    }
}

// ---------------------------------------------------------------------------
// QK on tensor cores. Block: 256 q x 64 n, 8 warps, warp tile 32q x 64n.
// Sr = QrKr + QiKi ; Si = QrKi + (-Qi)Kr.  Split-tf32, 3 passes/product.
// (byte-identical to Round 9/10)
// ---------------------------------------------------------------------------
__global__ __launch_bounds__(256) void qk_mma()
{
    __shared__ uint32_t sB[4][32 * 72];

    const int bh = blockIdx.z;
    const int q0 = blockIdx.y * 256;
    const int n0 = blockIdx.x * 64;
    const int tid = threadIdx.x;
    const int warp = tid >> 5, lane = tid & 31;
    const int g = lane >> 2, t = lane & 3;
    const int qw = q0 + warp * 32;

    const size_t hb = (size_t)bh * QL * QDh;
    const uint32_t* QrH = g_Qh + hb;
    const uint32_t* QrL = g_Ql + hb;
    const uint32_t* QiH = g_Qh + RIOFF + hb;
    const uint32_t* QiL = g_Ql + RIOFF + hb;
    const uint32_t* Ks[4] = { g_Kh + hb, g_Kl + hb,
                              g_Kh + RIOFF + hb, g_Kl + RIOFF + hb };

    float Sr[2][8][4], Si[2][8][4];
    #pragma unroll
    for (int m = 0; m < 2; m++)
        #pragma unroll
        for (int i = 0; i < 8; i++)
            #pragma unroll
            for (int j = 0; j < 4; j++) { Sr[m][i][j] = 0.f; Si[m][i][j] = 0.f; }

    #pragma unroll
    for (int kc = 0; kc < 2; ++kc) {
        __syncthreads();
        #pragma unroll
        for (int it = 0; it < 2; ++it) {
            int s = tid + it * 256;
            int n = s & 63, dg = s >> 6;
            #pragma unroll
            for (int p = 0; p < 4; p++) {
                uint4 v = *(const uint4*)(Ks[p] + (size_t)(n0 + n) * QDh + kc * 32 + dg * 4);
                sB[p][(dg * 4 + 0) * 72 + n] = v.x;
                sB[p][(dg * 4 + 1) * 72 + n] = v.y;
                sB[p][(dg * 4 + 2) * 72 + n] = v.z;
                sB[p][(dg * 4 + 3) * 72 + n] = v.w;
            }
        }
        __syncthreads();

        #pragma unroll
        for (int ks = 0; ks < 4; ++ks) {
            const int kd = kc * 32 + ks * 8 + t;
            uint32_t qrh[2][4], qrl[2][4], qih[2][4], qil[2][4], nih[2][4], nil_[2][4];
            #pragma unroll
            for (int m = 0; m < 2; m++) {
                const size_t ra = (size_t)(qw + m * 16 + g) * QDh + kd;
                const size_t rb = ra + (size_t)8 * QDh;
                qrh[m][0] = QrH[ra]; qrh[m][1] = QrH[rb]; qrh[m][2] = QrH[ra + 4]; qrh[m][3] = QrH[rb + 4];
                qrl[m][0] = QrL[ra]; qrl[m][1] = QrL[rb]; qrl[m][2] = QrL[ra + 4]; qrl[m][3] = QrL[rb + 4];
                qih[m][0] = QiH[ra]; qih[m][1] = QiH[rb]; qih[m][2] = QiH[ra + 4]; qih[m][3] = QiH[rb + 4];
                qil[m][0] = QiL[ra]; qil[m][1] = QiL[rb]; qil[m][2] = QiL[ra + 4]; qil[m][3] = QiL[rb + 4];
                #pragma unroll
                for (int e = 0; e < 4; e++) {
                    nih[m][e]  = qih[m][e] ^ 0x80000000u;
                    nil_[m][e] = qil[m][e] ^ 0x80000000u;
                }
            }
            const int rr1 = (ks * 8 + t) * 72, rr2 = (ks * 8 + t + 4) * 72;
            #pragma unroll
            for (int nt = 0; nt < 8; ++nt) {
                const int cb = nt * 8 + g;
                uint32_t krh0 = sB[0][rr1 + cb], krh1 = sB[0][rr2 + cb];
                uint32_t krl0 = sB[1][rr1 + cb], krl1 = sB[1][rr2 + cb];
                uint32_t kih0 = sB[2][rr1 + cb], kih1 = sB[2][rr2 + cb];
                uint32_t kil0 = sB[3][rr1 + cb], kil1 = sB[3][rr2 + cb];
                #pragma unroll
                for (int m = 0; m < 2; m++) {
                    mma8(Sr[m][nt], qrh[m], krh0, krh1);
                    mma8(Sr[m][nt], qrh[m], krl0, krl1);
                    mma8(Sr[m][nt], qrl[m], krh0, krh1);
                    mma8(Sr[m][nt], qih[m], kih0, kih1);
                    mma8(Sr[m][nt], qih[m], kil0, kil1);
                    mma8(Sr[m][nt], qil[m], kih0, kih1);
                    mma8(Si[m][nt], qrh[m], kih0, kih1);
                    mma8(Si[m][nt], qrh[m], kil0, kil1);
                    mma8(Si[m][nt], qrl[m], kih0, kih1);
                    mma8(Si[m][nt], nih[m], krh0, krh1);
                    mma8(Si[m][nt], nih[m], krl0, krl1);
                    mma8(Si[m][nt], nil_[m], krh0, krh1);
                }
            }
        }
    }

    const size_t base = (size_t)bh * QL * QL;
    #pragma unroll
    for (int m = 0; m < 2; m++) {
        #pragma unroll
        for (int nt = 0; nt < 8; ++nt) {
            const int col = n0 + nt * 8 + 2 * t;
            size_t o0 = base + (size_t)(qw + m * 16 + g) * QL + col;
            size_t o1 = base + (size_t)(qw + m * 16 + g + 8) * QL + col;
            *(float2*)(g_Sr + o0) = make_float2(Sr[m][nt][0], Sr[m][nt][1]);
            *(float2*)(g_Si + o0) = make_float2(Si[m][nt][0], Si[m][nt][1]);
            *(float2*)(g_Sr + o1) = make_float2(Sr[m][nt][2], Sr[m][nt][3]);
            *(float2*)(g_Si + o1) = make_float2(Si[m][nt][2], Si[m][nt][3]);
        }
    }
}

// ---------------------------------------------------------------------------
// Softmax stats only: m = max_k s, il = 1/sum_k exp(s-m); s = (Sr^2+Si^2)/8.
// Reads Sr/Si; writes g_m/g_il. FMA-pipe exp. One block (256 thr) per row.
// ---------------------------------------------------------------------------
__global__ __launch_bounds__(256) void stats_kernel()
{
    const int row = blockIdx.x;
    const float* sr = g_Sr + (size_t)row * QL;
    const float* si = g_Si + (size_t)row * QL;
    const int tid = threadIdx.x;

    float e[8];
    float mx = -3.4e38f;
    #pragma unroll
    for (int i = 0; i < 8; i++) {
        int k = i * 256 + tid;
        float a = sr[k], b = si[k];
        float s = (a * a + b * b) * 0.125f;
        e[i] = s;
        mx = fmaxf(mx, s);
    }

    __shared__ float red[256];
    red[tid] = mx;
    __syncthreads();
    #pragma unroll
    for (int off = 128; off > 0; off >>= 1) {
        if (tid < off) red[tid] = fmaxf(red[tid], red[tid + off]);
        __syncthreads();
    }
    const float m = red[0];
    __syncthreads();

    float sum = 0.f;
    #pragma unroll
    for (int i = 0; i < 8; i++) sum += exp_neg_fast(e[i] - m);
    red[tid] = sum;
    __syncthreads();
    #pragma unroll
    for (int off = 128; off > 0; off >>= 1) {
        if (tid < off) red[tid] += red[tid + off];
        __syncthreads();
    }
    if (tid == 0) { g_m[row] = m; g_il[row] = 1.0f / red[0]; }
}

// ---------------------------------------------------------------------------
// AV on tensor cores, fused with softmax+phase per element:
// A = exp((Sr^2+Si^2)/8 - m)*il ; attn out (wn==0 lanes) ;
// Pc = A*Sr*rsqrt(r2), Ps = A*Si*rsqrt(r2) computed in-register in A-frag
// positions (FMA-pipe exp/rsqrt, no MUFU).
// Block: 128 q x Dh=64; 8 warps = 4 wq (32q, 2 m-tiles) x 2 wn (32dh).
// Or = Pc*Vr + (-Ps)*Vi ; Oi = Ps*Vr + Pc*Vi.  Split-tf32, 3 passes.
// ---------------------------------------------------------------------------
__global__ __launch_bounds__(256) void av_mma(float* __restrict__ attn)
{
    __shared__ uint32_t sV[4][32 * 72];

    const int bh = blockIdx.y;
    const int q0 = blockIdx.x * 128;
    const int tid = threadIdx.x;
    const int warp = tid >> 5, lane = tid & 31;
    const int wq = warp >> 1, wn = warp & 1;
    const int g = lane >> 2, t = lane & 3;
    const int qw = q0 + wq * 32;

    const size_t hb = (size_t)bh * QL * QDh;
    const uint32_t* Vp[4] = { g_Vh + hb, g_Vl + hb,
                              g_Vh + RIOFF + hb, g_Vl + RIOFF + hb };

    const size_t sbase = (size_t)bh * QL * QL;
    const float* Sr = g_Sr + sbase;
    const float* Si = g_Si + sbase;
    float* at = attn + sbase;

    // row stats for the 4 rows this thread touches: [m][e&1]
    float mrow[2][2], ilrow[2][2];
    #pragma unroll
    for (int m = 0; m < 2; m++)
        #pragma unroll
        for (int h2 = 0; h2 < 2; h2++) {
            const int row = qw + m * 16 + g + h2 * 8;
            mrow[m][h2]  = g_m[bh * QL + row];
            ilrow[m][h2] = g_il[bh * QL + row];
        }

    float Or[2][4][4], Oi[2][4][4];
    #pragma unroll
    for (int m = 0; m < 2; m++)
        #pragma unroll
        for (int i = 0; i < 4; i++)
            #pragma unroll
            for (int j = 0; j < 4; j++) { Or[m][i][j] = 0.f; Oi[m][i][j] = 0.f; }

    for (int k0 = 0; k0 < QL; k0 += 32) {
        __syncthreads();
        #pragma unroll
        for (int it = 0; it < 2; ++it) {
            int idx = tid + it * 256;
            int jl = idx >> 4, dq = (idx & 15) * 4;
            #pragma unroll
            for (int p = 0; p < 4; p++) {
                uint4 v = *(const uint4*)(Vp[p] + (size_t)(k0 + jl) * QDh + dq);
                sV[p][jl * 72 + dq + 0] = v.x;
                sV[p][jl * 72 + dq + 1] = v.y;
                sV[p][jl * 72 + dq + 2] = v.z;
                sV[p][jl * 72 + dq + 3] = v.w;
            }
        }
        __syncthreads();

        #pragma unroll
        for (int ks = 0; ks < 4; ++ks) {
            uint32_t ach[2][4], acl[2][4], ash[2][4], asl[2][4], nsh[2][4], nsl[2][4];
            #pragma unroll
            for (int m = 0; m < 2; m++) {
                #pragma unroll
                for (int e = 0; e < 4; ++e) {
                    const int j = k0 + ks * 8 + t + (e >> 1) * 4;
                    const int h2 = e & 1;
                    const int row = qw + m * 16 + g + h2 * 8;
                    float a = Sr[(size_t)row * QL + j];
                    float b = Si[(size_t)row * QL + j];
                    float r2 = a * a + b * b;
                    float A = exp_neg_fast(fmaf(r2, 0.125f, -mrow[m][h2])) * ilrow[m][h2];
                    if (wn == 0)
                        at[(size_t)row * QL + j] = A;
                    float pc, ps;
                    if (r2 > 0.f) {
                        float inv = rsqrt_fast(r2);
                        pc = A * a * inv; ps = A * b * inv;
                    } else { pc = A; ps = 0.f; }
                    f2tf(pc, ach[m][e], acl[m][e]);
                    f2tf(ps, ash[m][e], asl[m][e]);
                    nsh[m][e] = ash[m][e] ^ 0x80000000u;
                    nsl[m][e] = asl[m][e] ^ 0x80000000u;
                }
            }
            const int rr1 = (ks * 8 + t) * 72, rr2 = (ks * 8 + t + 4) * 72;
            #pragma unroll
            for (int nt = 0; nt < 4; ++nt) {
                const int cb = wn * 32 + nt * 8 + g;
                uint32_t vrh0 = sV[0][rr1 + cb], vrh1 = sV[0][rr2 + cb];
                uint32_t vrl0 = sV[1][rr1 + cb], vrl1 = sV[1][rr2 + cb];
                uint32_t vih0 = sV[2][rr1 + cb], vih1 = sV[2][rr2 + cb];
                uint32_t vil0 = sV[3][rr1 + cb], vil1 = sV[3][rr2 + cb];
                #pragma unroll
                for (int m = 0; m < 2; m++) {
                    mma8(Or[m][nt], ach[m], vrh0, vrh1);
                    mma8(Or[m][nt], ach[m], vrl0, vrl1);
                    mma8(Or[m][nt], acl[m], vrh0, vrh1);
                    mma8(Or[m][nt], nsh[m], vih0, vih1);
                    mma8(Or[m][nt], nsh[m], vil0, vil1);
                    mma8(Or[m][nt], nsl[m], vih0, vih1);
                    mma8(Oi[m][nt], ash[m], vrh0, vrh1);
                    mma8(Oi[m][nt], ash[m], vrl0, vrl1);
                    mma8(Oi[m][nt], asl[m], vrh0, vrh1);
                    mma8(Oi[m][nt], ach[m], vih0, vih1);
                    mma8(Oi[m][nt], ach[m], vil0, vil1);
                    mma8(Oi[m][nt], acl[m], vih0, vih1);
                }
            }
        }
    }

    const int b = bh >> 3, h = bh & 7;
    #pragma unroll
    for (int m = 0; m < 2; m++) {
        const int r0 = qw + m * 16 + g, r1 = r0 + 8;
        #pragma unroll
        for (int nt = 0; nt < 4; ++nt) {
            const int dh = wn * 32 + nt * 8 + 2 * t;
            size_t o0 = ((size_t)b * QL + r0) * QD + h * QDh + dh;
            size_t o1 = ((size_t)b * QL + r1) * QD + h * QDh + dh;
            *(float2*)(g_Or + o0) = make_float2(Or[m][nt][0], Or[m][nt][1]);
            *(float2*)(g_Oi + o0) = make_float2(Oi[m][nt][0], Oi[m][nt][1]);
            *(float2*)(g_Or + o1) = make_float2(Or[m][nt][2], Or[m][nt][3]);
            *(float2*)(g_Oi + o1) = make_float2(Oi[m][nt][2], Oi[m][nt][3]);
        }
    }
}

// ---------------------------------------------------------------------------

extern "C" void kernel_launch(void* const* d_in, const int* in_sizes, int n_in,
                              void* d_out, int out_size)
{
    const float* wr = (const float*)d_in[0];
    const float* wi = (const float*)d_in[1];
    const float* Wq = (const float*)d_in[2];
    const float* bq = (const float*)d_in[3];
    const float* Wk = (const float*)d_in[4];
    const float* bk = (const float*)d_in[5];
    const float* Wv = (const float*)d_in[6];
    const float* bv = (const float*)d_in[7];
    const float* Wo = (const float*)d_in[8];
    const float* bo = (const float*)d_in[9];

    float* out      = (float*)d_out;
    float* out_real = out;
    float* out_imag = out + (size_t)QB * QL * QD;
    float* attn     = out + (size_t)2 * QB * QL * QD;

    dim3 gProj(4, 64);
    dim3 gOut(4, 32);

    proj_mma<0><<<gProj, 256>>>(wr, wi, Wq, bq, nullptr, 0);
    proj_mma<0><<<gProj, 256>>>(wr, wi, Wk, bk, nullptr, 1);
    proj_mma<0><<<gProj, 256>>>(wr, wi, Wv, bv, nullptr, 2);

    qk_mma<<<dim3(32, 8, 16), 256>>>();
    stats_kernel<<<QBH * QL, 256>>>();
    av_mma<<<dim3(16, 16), 256>>>(attn);

    proj_mma<1><<<gOut, 256>>>(nullptr, nullptr, Wo, bo, out_real, 0);
    proj_mma<1><<<gOut, 256>>>(nullptr, nullptr, Wo, bo, out_imag, 1);
}

// round 13
// speedup vs baseline: 1.4115x; 1.4115x over previous
#include <cuda_runtime.h>
#include <math.h>
#include <stdint.h>

namespace {
constexpr int QB = 2, QL = 2048, QD = 512, QH = 8, QDh = 64;
constexpr int QBH = QB * QH;
constexpr size_t RIOFF = (size_t)QBH * QL * QDh;
constexpr size_t QSZ   = 2 * RIOFF;
constexpr size_t SSZ   = (size_t)QBH * QL * QL;
}

__device__ uint32_t g_Qh[QSZ], g_Ql[QSZ];
__device__ uint32_t g_Kh[QSZ], g_Kl[QSZ];
__device__ uint32_t g_Vh[QSZ], g_Vl[QSZ];
__device__ float g_Sr[SSZ], g_Si[SSZ];   // after phase_kernel: Pc, Ps
__device__ float g_Or[(size_t)QB * QL * QD], g_Oi[(size_t)QB * QL * QD];

__device__ __forceinline__ uint32_t tf32h(float x) {
    uint32_t u; asm("cvt.rna.tf32.f32 %0, %1;" : "=r"(u) : "f"(x)); return u;
}
__device__ __forceinline__ void f2tf(float x, uint32_t& h, uint32_t& l) {
    h = tf32h(x);
    l = tf32h(x - __uint_as_float(h));
}
__device__ __forceinline__ void mma8(float c[4], const uint32_t a[4],
                                     uint32_t b0, uint32_t b1) {
    asm volatile(
        "mma.sync.aligned.m16n8k8.row.col.f32.tf32.tf32.f32 "
        "{%0,%1,%2,%3},{%4,%5,%6,%7},{%8,%9},{%0,%1,%2,%3};"
        : "+f"(c[0]), "+f"(c[1]), "+f"(c[2]), "+f"(c[3])
        : "r"(a[0]), "r"(a[1]), "r"(a[2]), "r"(a[3]), "r"(b0), "r"(b1));
}

// exp(x) for x <= 0, FMA-pipe only (no MUFU). ~1e-7 relative accuracy.
__device__ __forceinline__ float exp_neg_fast(float x) {
    const float LOG2E = 1.4426950408889634f;
    float t = x * LOG2E;
    float fl = floorf(t);
    float r = t - fl;
    float y = r * 0.6931471805599453f;
    float p = 2.4801587301587301e-5f;
    p = fmaf(p, y, 1.9841269841269841e-4f);
    p = fmaf(p, y, 1.3888888888888889e-3f);
    p = fmaf(p, y, 8.3333333333333333e-3f);
    p = fmaf(p, y, 4.1666666666666664e-2f);
    p = fmaf(p, y, 1.6666666666666666e-1f);
    p = fmaf(p, y, 5.0e-1f);
    p = fmaf(p, y, 1.0f);
    p = fmaf(p, y, 1.0f);
    int ni = (int)fl;
    ni = (ni < -127) ? -127 : ni;
    float sc = __int_as_float((uint32_t)(ni + 127) << 23);
    return p * sc;
}

__device__ __forceinline__ float rsqrt_fast(float x) {
    float y = __int_as_float(0x5f375a86u - (__float_as_uint(x) >> 1));
    y = y * fmaf(-0.5f * x, y * y, 1.5f);
    y = y * fmaf(-0.5f * x, y * y, 1.5f);
    return y;
}

// ---------------------------------------------------------------------------
// Projections on tensor cores (split-tf32, 3 passes).
// Block 128x128, 8 warps = 4 wq x 2 wn, warp tile 32x64.
// MODE 0: scatter-store to tf32 hi/lo planes of Q/K/V (sel).
// MODE 1: X = g_Or/g_Oi; row-major float out.
// ---------------------------------------------------------------------------
template <int MODE>
__global__ __launch_bounds__(256) void proj_mma(
    const float* __restrict__ X0, const float* __restrict__ X1,
    const float* __restrict__ Wt, const float* __restrict__ bias,
    float* __restrict__ Yext, int sel)
{
    __shared__ uint32_t sA[2][16 * 132];
    __shared__ uint32_t sW[2][16 * 132];

    const int tid = threadIdx.x;
    const int r0 = blockIdx.y * 128;
    const int c0 = blockIdx.x * 128;

    const float* X;
    int rbase = r0;
    if (MODE == 0) {
        if (r0 >= 4096) { X = X1; rbase = r0 - 4096; }
        else            { X = X0; }
    } else {
        X = sel ? g_Oi : g_Or;
    }

    const int warp = tid >> 5, lane = tid & 31;
    const int wq = warp >> 1, wn = warp & 1;
    const int g = lane >> 2, t = lane & 3;

    const int lr = tid >> 1;
    const int lc0 = (tid & 1) << 2;

    float C[2][8][4];
    #pragma unroll
    for (int m = 0; m < 2; m++)
        #pragma unroll
        for (int i = 0; i < 8; i++)
            #pragma unroll
            for (int j = 0; j < 4; j++) C[m][i][j] = 0.f;

    for (int k0 = 0; k0 < 512; k0 += 16) {
        __syncthreads();
        #pragma unroll
        for (int it = 0; it < 2; ++it) {
            const int kk = lc0 + it * 8;
            float4 a = *(const float4*)(X  + (size_t)(rbase + lr) * 512 + k0 + kk);
            float4 w = *(const float4*)(Wt + (size_t)(c0 + lr) * 512 + k0 + kk);
            uint32_t h, l;
            f2tf(a.x, h, l); sA[0][(kk + 0) * 132 + lr] = h; sA[1][(kk + 0) * 132 + lr] = l;
            f2tf(a.y, h, l); sA[0][(kk + 1) * 132 + lr] = h; sA[1][(kk + 1) * 132 + lr] = l;
            f2tf(a.z, h, l); sA[0][(kk + 2) * 132 + lr] = h; sA[1][(kk + 2) * 132 + lr] = l;
            f2tf(a.w, h, l); sA[0][(kk + 3) * 132 + lr] = h; sA[1][(kk + 3) * 132 + lr] = l;
            f2tf(w.x, h, l); sW[0][(kk + 0) * 132 + lr] = h; sW[1][(kk + 0) * 132 + lr] = l;
            f2tf(w.y, h, l); sW[0][(kk + 1) * 132 + lr] = h; sW[1][(kk + 1) * 132 + lr] = l;
            f2tf(w.z, h, l); sW[0][(kk + 2) * 132 + lr] = h; sW[1][(kk + 2) * 132 + lr] = l;
            f2tf(w.w, h, l); sW[0][(kk + 3) * 132 + lr] = h; sW[1][(kk + 3) * 132 + lr] = l;
        }
        __syncthreads();

        #pragma unroll
        for (int ks = 0; ks < 2; ++ks) {
            const int kd = ks * 8 + t;
            uint32_t ah[2][4], al[2][4];
            #pragma unroll
            for (int m = 0; m < 2; m++) {
                const int row = wq * 32 + m * 16 + g;
                ah[m][0] = sA[0][kd * 132 + row];
                ah[m][1] = sA[0][kd * 132 + row + 8];
                ah[m][2] = sA[0][(kd + 4) * 132 + row];
                ah[m][3] = sA[0][(kd + 4) * 132 + row + 8];
                al[m][0] = sA[1][kd * 132 + row];
                al[m][1] = sA[1][kd * 132 + row + 8];
                al[m][2] = sA[1][(kd + 4) * 132 + row];
                al[m][3] = sA[1][(kd + 4) * 132 + row + 8];
            }
            #pragma unroll
            for (int nt = 0; nt < 8; ++nt) {
                const int cb = wn * 64 + nt * 8 + g;
                uint32_t bh0 = sW[0][kd * 132 + cb];
                uint32_t bh1 = sW[0][(kd + 4) * 132 + cb];
                uint32_t bl0 = sW[1][kd * 132 + cb];
                uint32_t bl1 = sW[1][(kd + 4) * 132 + cb];
                #pragma unroll
                for (int m = 0; m < 2; m++) {
                    mma8(C[m][nt], ah[m], bh0, bh1);
                    mma8(C[m][nt], ah[m], bl0, bl1);
                    mma8(C[m][nt], al[m], bh0, bh1);
                }
            }
        }
    }

    #pragma unroll
    for (int m = 0; m < 2; m++) {
        const int row0 = r0 + wq * 32 + m * 16 + g;
        #pragma unroll
        for (int nt = 0; nt < 8; ++nt) {
            const int col = c0 + wn * 64 + nt * 8 + 2 * t;
            const float b0 = bias[col], b1 = bias[col + 1];
            float v00 = C[m][nt][0] + b0, v01 = C[m][nt][1] + b1;
            float v10 = C[m][nt][2] + b0, v11 = C[m][nt][3] + b1;
            if (MODE == 0) {
                uint32_t* dH = (sel == 0) ? g_Qh : (sel == 1) ? g_Kh : g_Vh;
                uint32_t* dL = (sel == 0) ? g_Ql : (sel == 1) ? g_Kl : g_Vl;
                #pragma unroll
                for (int e = 0; e < 4; ++e) {
                    const int r = row0 + (e >> 1) * 8;
                    const int c = col + (e & 1);
                    const float v = (e == 0) ? v00 : (e == 1) ? v01 : (e == 2) ? v10 : v11;
                    const int ri = r >> 12;
                    const int bl = r & 4095;
                    const int bb = bl >> 11;
                    const int l  = bl & 2047;
                    const int h  = c >> 6;
                    const int dh = c & 63;
                    size_t idx = ((((size_t)ri * QB + bb) * QH + h) * QL + l) * QDh + dh;
                    uint32_t hh, ll; f2tf(v, hh, ll);
                    dH[idx] = hh; dL[idx] = ll;
                }
            } else {
                *(float2*)(Yext + (size_t)row0 * 512 + col) = make_float2(v00, v01);
                *(float2*)(Yext + (size_t)(row0 + 8) * 512 + col) = make_float2(v10, v11);
            }
        }
    }
}

// ---------------------------------------------------------------------------
// QK on tensor cores. Block: 256 q x 64 n, 8 warps, warp tile 32q x 64n.
// Sr = QrKr + QiKi ; Si = QrKi + (-Qi)Kr.  Split-tf32, 3 passes/product.
// ---------------------------------------------------------------------------
__global__ __launch_bounds__(256) void qk_mma()
{
    __shared__ uint32_t sB[4][32 * 72];

    const int bh = blockIdx.z;
    const int q0 = blockIdx.y * 256;
    const int n0 = blockIdx.x * 64;
    const int tid = threadIdx.x;
    const int warp = tid >> 5, lane = tid & 31;
    const int g = lane >> 2, t = lane & 3;
    const int qw = q0 + warp * 32;

    const size_t hb = (size_t)bh * QL * QDh;
    const uint32_t* QrH = g_Qh + hb;
    const uint32_t* QrL = g_Ql + hb;
    const uint32_t* QiH = g_Qh + RIOFF + hb;
    const uint32_t* QiL = g_Ql + RIOFF + hb;
    const uint32_t* Ks[4] = { g_Kh + hb, g_Kl + hb,
                              g_Kh + RIOFF + hb, g_Kl + RIOFF + hb };

    float Sr[2][8][4], Si[2][8][4];
    #pragma unroll
    for (int m = 0; m < 2; m++)
        #pragma unroll
        for (int i = 0; i < 8; i++)
            #pragma unroll
            for (int j = 0; j < 4; j++) { Sr[m][i][j] = 0.f; Si[m][i][j] = 0.f; }

    #pragma unroll
    for (int kc = 0; kc < 2; ++kc) {
        __syncthreads();
        #pragma unroll
        for (int it = 0; it < 2; ++it) {
            int s = tid + it * 256;
            int n = s & 63, dg = s >> 6;
            #pragma unroll
            for (int p = 0; p < 4; p++) {
                uint4 v = *(const uint4*)(Ks[p] + (size_t)(n0 + n) * QDh + kc * 32 + dg * 4);
                sB[p][(dg * 4 + 0) * 72 + n] = v.x;
                sB[p][(dg * 4 + 1) * 72 + n] = v.y;
                sB[p][(dg * 4 + 2) * 72 + n] = v.z;
                sB[p][(dg * 4 + 3) * 72 + n] = v.w;
            }
        }
        __syncthreads();

        #pragma unroll
        for (int ks = 0; ks < 4; ++ks) {
            const int kd = kc * 32 + ks * 8 + t;
            uint32_t qrh[2][4], qrl[2][4], qih[2][4], qil[2][4], nih[2][4], nil_[2][4];
            #pragma unroll
            for (int m = 0; m < 2; m++) {
                const size_t ra = (size_t)(qw + m * 16 + g) * QDh + kd;
                const size_t rb = ra + (size_t)8 * QDh;
                qrh[m][0] = QrH[ra]; qrh[m][1] = QrH[rb]; qrh[m][2] = QrH[ra + 4]; qrh[m][3] = QrH[rb + 4];
                qrl[m][0] = QrL[ra]; qrl[m][1] = QrL[rb]; qrl[m][2] = QrL[ra + 4]; qrl[m][3] = QrL[rb + 4];
                qih[m][0] = QiH[ra]; qih[m][1] = QiH[rb]; qih[m][2] = QiH[ra + 4]; qih[m][3] = QiH[rb + 4];
                qil[m][0] = QiL[ra]; qil[m][1] = QiL[rb]; qil[m][2] = QiL[ra + 4]; qil[m][3] = QiL[rb + 4];
                #pragma unroll
                for (int e = 0; e < 4; e++) {
                    nih[m][e]  = qih[m][e] ^ 0x80000000u;
                    nil_[m][e] = qil[m][e] ^ 0x80000000u;
                }
            }
            const int rr1 = (ks * 8 + t) * 72, rr2 = (ks * 8 + t + 4) * 72;
            #pragma unroll
            for (int nt = 0; nt < 8; ++nt) {
                const int cb = nt * 8 + g;
                uint32_t krh0 = sB[0][rr1 + cb], krh1 = sB[0][rr2 + cb];
                uint32_t krl0 = sB[1][rr1 + cb], krl1 = sB[1][rr2 + cb];
                uint32_t kih0 = sB[2][rr1 + cb], kih1 = sB[2][rr2 + cb];
                uint32_t kil0 = sB[3][rr1 + cb], kil1 = sB[3][rr2 + cb];
                #pragma unroll
                for (int m = 0; m < 2; m++) {
                    mma8(Sr[m][nt], qrh[m], krh0, krh1);
                    mma8(Sr[m][nt], qrh[m], krl0, krl1);
                    mma8(Sr[m][nt], qrl[m], krh0, krh1);
                    mma8(Sr[m][nt], qih[m], kih0, kih1);
                    mma8(Sr[m][nt], qih[m], kil0, kil1);
                    mma8(Sr[m][nt], qil[m], kih0, kih1);
                    mma8(Si[m][nt], qrh[m], kih0, kih1);
                    mma8(Si[m][nt], qrh[m], kil0, kil1);
                    mma8(Si[m][nt], qrl[m], kih0, kih1);
                    mma8(Si[m][nt], nih[m], krh0, krh1);
                    mma8(Si[m][nt], nih[m], krl0, krl1);
                    mma8(Si[m][nt], nil_[m], krh0, krh1);
                }
            }
        }
    }

    const size_t base = (size_t)bh * QL * QL;
    #pragma unroll
    for (int m = 0; m < 2; m++) {
        #pragma unroll
        for (int nt = 0; nt < 8; ++nt) {
            const int col = n0 + nt * 8 + 2 * t;
            size_t o0 = base + (size_t)(qw + m * 16 + g) * QL + col;
            size_t o1 = base + (size_t)(qw + m * 16 + g + 8) * QL + col;
            *(float2*)(g_Sr + o0) = make_float2(Sr[m][nt][0], Sr[m][nt][1]);
            *(float2*)(g_Si + o0) = make_float2(Si[m][nt][0], Si[m][nt][1]);
            *(float2*)(g_Sr + o1) = make_float2(Sr[m][nt][2], Sr[m][nt][3]);
            *(float2*)(g_Si + o1) = make_float2(Si[m][nt][2], Si[m][nt][3]);
        }
    }
}

// ---------------------------------------------------------------------------
// Fused softmax + phase: per row compute m, sum; write attention A to output,
// and overwrite g_Sr/g_Si in place with Pc = A*cos(phase), Ps = A*sin(phase).
// All exp/rsqrt on the FMA pipe (no MUFU).  One block (256 thr) per row.
// ---------------------------------------------------------------------------
__global__ __launch_bounds__(256) void phase_kernel(float* __restrict__ attn)
{
    const int row = blockIdx.x;
    float* sr = g_Sr + (size_t)row * QL;
    float* si = g_Si + (size_t)row * QL;
    float* at = attn + (size_t)row * QL;
    const int tid = threadIdx.x;

    float a[8], b[8], e[8];
    float mx = -3.4e38f;
    #pragma unroll
    for (int i = 0; i < 8; i++) {
        int k = i * 256 + tid;
        a[i] = sr[k]; b[i] = si[k];
        float s = (a[i] * a[i] + b[i] * b[i]) * 0.125f;
        e[i] = s;
        mx = fmaxf(mx, s);
    }

    __shared__ float red[256];
    red[tid] = mx;
    __syncthreads();
    #pragma unroll
    for (int off = 128; off > 0; off >>= 1) {
        if (tid < off) red[tid] = fmaxf(red[tid], red[tid + off]);
        __syncthreads();
    }
    const float m = red[0];
    __syncthreads();

    float sum = 0.f;
    #pragma unroll
    for (int i = 0; i < 8; i++) {
        e[i] = exp_neg_fast(e[i] - m);
        sum += e[i];
    }
    red[tid] = sum;
    __syncthreads();
    #pragma unroll
    for (int off = 128; off > 0; off >>= 1) {
        if (tid < off) red[tid] += red[tid + off];
        __syncthreads();
    }
    const float il = 1.0f / red[0];

    #pragma unroll
    for (int i = 0; i < 8; i++) {
        int k = i * 256 + tid;
        float A = e[i] * il;
        at[k] = A;
        float r2 = a[i] * a[i] + b[i] * b[i];
        float cr = 1.f, sn = 0.f;
        if (r2 > 0.f) {
            float inv = rsqrt_fast(r2);
            cr = a[i] * inv; sn = b[i] * inv;
        }
        sr[k] = A * cr;
        si[k] = A * sn;
    }
}

// ---------------------------------------------------------------------------
// AV on tensor cores. P = (Pc, Ps) read from g_Sr/g_Si (phase_kernel output).
// Block: 128 q rows x Dh=64; 8 warps = 4 q-warps (32q each, 2 m-tiles) x
// 2 n-warps (32dh).
// P uses single tf32 (hi only, rel err ~2^-11 on O — inside budget);
// V keeps hi/lo split. 2 passes per product -> 8 MMAs per (nt,m).
// Or = Pc*Vr + (-Ps)*Vi ; Oi = Ps*Vr + Pc*Vi.
// ---------------------------------------------------------------------------
__global__ __launch_bounds__(256) void av_mma()
{
    __shared__ uint32_t sV[4][32 * 72];

    const int bh = blockIdx.y;
    const int q0 = blockIdx.x * 128;
    const int tid = threadIdx.x;
    const int warp = tid >> 5, lane = tid & 31;
    const int wq = warp >> 1, wn = warp & 1;
    const int g = lane >> 2, t = lane & 3;
    const int qw = q0 + wq * 32;

    const size_t hb = (size_t)bh * QL * QDh;
    const uint32_t* Vp[4] = { g_Vh + hb, g_Vl + hb,
                              g_Vh + RIOFF + hb, g_Vl + RIOFF + hb };

    const size_t sbase = (size_t)bh * QL * QL;
    const float* Pc = g_Sr + sbase;
    const float* Ps = g_Si + sbase;

    float Or[2][4][4], Oi[2][4][4];
    #pragma unroll
    for (int m = 0; m < 2; m++)
        #pragma unroll
        for (int i = 0; i < 4; i++)
            #pragma unroll
            for (int j = 0; j < 4; j++) { Or[m][i][j] = 0.f; Oi[m][i][j] = 0.f; }

    for (int k0 = 0; k0 < QL; k0 += 32) {
        __syncthreads();
        #pragma unroll
        for (int it = 0; it < 2; ++it) {
            int idx = tid + it * 256;
            int jl = idx >> 4, dq = (idx & 15) * 4;
            #pragma unroll
            for (int p = 0; p < 4; p++) {
                uint4 v = *(const uint4*)(Vp[p] + (size_t)(k0 + jl) * QDh + dq);
                sV[p][jl * 72 + dq + 0] = v.x;
                sV[p][jl * 72 + dq + 1] = v.y;
                sV[p][jl * 72 + dq + 2] = v.z;
                sV[p][jl * 72 + dq + 3] = v.w;
            }
        }
        __syncthreads();

        #pragma unroll
        for (int ks = 0; ks < 4; ++ks) {
            uint32_t ach[2][4], ash[2][4], nsh[2][4];
            #pragma unroll
            for (int m = 0; m < 2; m++) {
                #pragma unroll
                for (int e = 0; e < 4; ++e) {
                    const int j = k0 + ks * 8 + t + (e >> 1) * 4;
                    const int row = qw + m * 16 + g + (e & 1) * 8;
                    float pc = Pc[(size_t)row * QL + j];
                    float ps = Ps[(size_t)row * QL + j];
                    ach[m][e] = tf32h(pc);
                    ash[m][e] = tf32h(ps);
                    nsh[m][e] = ash[m][e] ^ 0x80000000u;
                }
            }
            const int rr1 = (ks * 8 + t) * 72, rr2 = (ks * 8 + t + 4) * 72;
            #pragma unroll
            for (int nt = 0; nt < 4; ++nt) {
                const int cb = wn * 32 + nt * 8 + g;
                uint32_t vrh0 = sV[0][rr1 + cb], vrh1 = sV[0][rr2 + cb];
                uint32_t vrl0 = sV[1][rr1 + cb], vrl1 = sV[1][rr2 + cb];
                uint32_t vih0 = sV[2][rr1 + cb], vih1 = sV[2][rr2 + cb];
                uint32_t vil0 = sV[3][rr1 + cb], vil1 = sV[3][rr2 + cb];
                #pragma unroll
                for (int m = 0; m < 2; m++) {
                    mma8(Or[m][nt], ach[m], vrh0, vrh1);
                    mma8(Or[m][nt], ach[m], vrl0, vrl1);
                    mma8(Or[m][nt], nsh[m], vih0, vih1);
                    mma8(Or[m][nt], nsh[m], vil0, vil1);
                    mma8(Oi[m][nt], ash[m], vrh0, vrh1);
                    mma8(Oi[m][nt], ash[m], vrl0, vrl1);
                    mma8(Oi[m][nt], ach[m], vih0, vih1);
                    mma8(Oi[m][nt], ach[m], vil0, vil1);
                }
            }
        }
    }

    const int b = bh >> 3, h = bh & 7;
    #pragma unroll
    for (int m = 0; m < 2; m++) {
        const int r0 = qw + m * 16 + g, r1 = r0 + 8;
        #pragma unroll
        for (int nt = 0; nt < 4; ++nt) {
            const int dh = wn * 32 + nt * 8 + 2 * t;
            size_t o0 = ((size_t)b * QL + r0) * QD + h * QDh + dh;
            size_t o1 = ((size_t)b * QL + r1) * QD + h * QDh + dh;
            *(float2*)(g_Or + o0) = make_float2(Or[m][nt][0], Or[m][nt][1]);
            *(float2*)(g_Oi + o0) = make_float2(Oi[m][nt][0], Oi[m][nt][1]);
            *(float2*)(g_Or + o1) = make_float2(Or[m][nt][2], Or[m][nt][3]);
            *(float2*)(g_Oi + o1) = make_float2(Oi[m][nt][2], Oi[m][nt][3]);
        }
    }
}

// ---------------------------------------------------------------------------

extern "C" void kernel_launch(void* const* d_in, const int* in_sizes, int n_in,
                              void* d_out, int out_size)
{
    const float* wr = (const float*)d_in[0];
    const float* wi = (const float*)d_in[1];
    const float* Wq = (const float*)d_in[2];
    const float* bq = (const float*)d_in[3];
    const float* Wk = (const float*)d_in[4];
    const float* bk = (const float*)d_in[5];
    const float* Wv = (const float*)d_in[6];
    const float* bv = (const float*)d_in[7];
    const float* Wo = (const float*)d_in[8];
    const float* bo = (const float*)d_in[9];

    float* out      = (float*)d_out;
    float* out_real = out;
    float* out_imag = out + (size_t)QB * QL * QD;
    float* attn     = out + (size_t)2 * QB * QL * QD;

    dim3 gProj(4, 64);
    dim3 gOut(4, 32);

    proj_mma<0><<<gProj, 256>>>(wr, wi, Wq, bq, nullptr, 0);
    proj_mma<0><<<gProj, 256>>>(wr, wi, Wk, bk, nullptr, 1);
    proj_mma<0><<<gProj, 256>>>(wr, wi, Wv, bv, nullptr, 2);

    qk_mma<<<dim3(32, 8, 16), 256>>>();
    phase_kernel<<<QBH * QL, 256>>>(attn);
    av_mma<<<dim3(16, 16), 256>>>();

    proj_mma<1><<<gOut, 256>>>(nullptr, nullptr, Wo, bo, out_real, 0);
    proj_mma<1><<<gOut, 256>>>(nullptr, nullptr, Wo, bo, out_imag, 1);
}

// round 14
// speedup vs baseline: 1.4885x; 1.0545x over previous
#include <cuda_runtime.h>
#include <math.h>
#include <stdint.h>

namespace {
constexpr int QB = 2, QL = 2048, QD = 512, QH = 8, QDh = 64;
constexpr int QBH = QB * QH;
constexpr size_t RIOFF = (size_t)QBH * QL * QDh;
constexpr size_t QSZ   = 2 * RIOFF;
constexpr size_t SSZ   = (size_t)QBH * QL * QL;
}

__device__ uint32_t g_Qh[QSZ], g_Ql[QSZ];   // Q: fragment-major layout (see proj epilogue)
__device__ uint32_t g_Kh[QSZ], g_Kl[QSZ];   // K: row-major [bh][l][dh]
__device__ uint32_t g_Vh[QSZ], g_Vl[QSZ];   // V: row-major [bh][l][dh]
__device__ float g_Sr[SSZ], g_Si[SSZ];      // after phase_kernel: Pc, Ps
__device__ float g_Or[(size_t)QB * QL * QD], g_Oi[(size_t)QB * QL * QD];

__device__ __forceinline__ uint32_t tf32h(float x) {
    uint32_t u; asm("cvt.rna.tf32.f32 %0, %1;" : "=r"(u) : "f"(x)); return u;
}
__device__ __forceinline__ void f2tf(float x, uint32_t& h, uint32_t& l) {
    h = tf32h(x);
    l = tf32h(x - __uint_as_float(h));
}
__device__ __forceinline__ void mma8(float c[4], const uint32_t a[4],
                                     uint32_t b0, uint32_t b1) {
    asm volatile(
        "mma.sync.aligned.m16n8k8.row.col.f32.tf32.tf32.f32 "
        "{%0,%1,%2,%3},{%4,%5,%6,%7},{%8,%9},{%0,%1,%2,%3};"
        : "+f"(c[0]), "+f"(c[1]), "+f"(c[2]), "+f"(c[3])
        : "r"(a[0]), "r"(a[1]), "r"(a[2]), "r"(a[3]), "r"(b0), "r"(b1));
}

// exp(x) for x <= 0, FMA-pipe only (no MUFU). ~1e-7 relative accuracy.
__device__ __forceinline__ float exp_neg_fast(float x) {
    const float LOG2E = 1.4426950408889634f;
    float t = x * LOG2E;
    float fl = floorf(t);
    float r = t - fl;
    float y = r * 0.6931471805599453f;
    float p = 2.4801587301587301e-5f;
    p = fmaf(p, y, 1.9841269841269841e-4f);
    p = fmaf(p, y, 1.3888888888888889e-3f);
    p = fmaf(p, y, 8.3333333333333333e-3f);
    p = fmaf(p, y, 4.1666666666666664e-2f);
    p = fmaf(p, y, 1.6666666666666666e-1f);
    p = fmaf(p, y, 5.0e-1f);
    p = fmaf(p, y, 1.0f);
    p = fmaf(p, y, 1.0f);
    int ni = (int)fl;
    ni = (ni < -127) ? -127 : ni;
    float sc = __int_as_float((uint32_t)(ni + 127) << 23);
    return p * sc;
}

__device__ __forceinline__ float rsqrt_fast(float x) {
    float y = __int_as_float(0x5f375a86u - (__float_as_uint(x) >> 1));
    y = y * fmaf(-0.5f * x, y * y, 1.5f);
    y = y * fmaf(-0.5f * x, y * y, 1.5f);
    return y;
}

// Fragment-major Q index within one bh-plane (size QL*QDh):
// tile = l>>4, e = ((dh>>2)&1)*2 + ((l>>3)&1)
// idx = tile*1024 + (dh>>5)*512 + ((dh>>3)&3)*128 + (dh&3)*32 + (l&7)*4 + e
__device__ __forceinline__ uint32_t qfrag_idx(int l, int dh) {
    return (uint32_t)((l >> 4) * 1024 + ((dh >> 5)) * 512 + (((dh >> 3) & 3)) * 128
                      + (dh & 3) * 32 + (l & 7) * 4
                      + (((dh >> 2) & 1) * 2 + ((l >> 3) & 1)));
}

// ---------------------------------------------------------------------------
// Projections on tensor cores (split-tf32, 3 passes).
// Block 128x128, 8 warps = 4 wq x 2 wn, warp tile 32x64.
// MODE 0: scatter-store to tf32 hi/lo planes of Q (fragment-major) /
//         K / V (row-major) by sel.
// MODE 1: X = g_Or/g_Oi; row-major float out.
// ---------------------------------------------------------------------------
template <int MODE>
__global__ __launch_bounds__(256) void proj_mma(
    const float* __restrict__ X0, const float* __restrict__ X1,
    const float* __restrict__ Wt, const float* __restrict__ bias,
    float* __restrict__ Yext, int sel)
{
    __shared__ uint32_t sA[2][16 * 132];
    __shared__ uint32_t sW[2][16 * 132];

    const int tid = threadIdx.x;
    const int r0 = blockIdx.y * 128;
    const int c0 = blockIdx.x * 128;

    const float* X;
    int rbase = r0;
    if (MODE == 0) {
        if (r0 >= 4096) { X = X1; rbase = r0 - 4096; }
        else            { X = X0; }
    } else {
        X = sel ? g_Oi : g_Or;
    }

    const int warp = tid >> 5, lane = tid & 31;
    const int wq = warp >> 1, wn = warp & 1;
    const int g = lane >> 2, t = lane & 3;

    const int lr = tid >> 1;
    const int lc0 = (tid & 1) << 2;

    float C[2][8][4];
    #pragma unroll
    for (int m = 0; m < 2; m++)
        #pragma unroll
        for (int i = 0; i < 8; i++)
            #pragma unroll
            for (int j = 0; j < 4; j++) C[m][i][j] = 0.f;

    for (int k0 = 0; k0 < 512; k0 += 16) {
        __syncthreads();
        #pragma unroll
        for (int it = 0; it < 2; ++it) {
            const int kk = lc0 + it * 8;
            float4 a = *(const float4*)(X  + (size_t)(rbase + lr) * 512 + k0 + kk);
            float4 w = *(const float4*)(Wt + (size_t)(c0 + lr) * 512 + k0 + kk);
            uint32_t h, l;
            f2tf(a.x, h, l); sA[0][(kk + 0) * 132 + lr] = h; sA[1][(kk + 0) * 132 + lr] = l;
            f2tf(a.y, h, l); sA[0][(kk + 1) * 132 + lr] = h; sA[1][(kk + 1) * 132 + lr] = l;
            f2tf(a.z, h, l); sA[0][(kk + 2) * 132 + lr] = h; sA[1][(kk + 2) * 132 + lr] = l;
            f2tf(a.w, h, l); sA[0][(kk + 3) * 132 + lr] = h; sA[1][(kk + 3) * 132 + lr] = l;
            f2tf(w.x, h, l); sW[0][(kk + 0) * 132 + lr] = h; sW[1][(kk + 0) * 132 + lr] = l;
            f2tf(w.y, h, l); sW[0][(kk + 1) * 132 + lr] = h; sW[1][(kk + 1) * 132 + lr] = l;
            f2tf(w.z, h, l); sW[0][(kk + 2) * 132 + lr] = h; sW[1][(kk + 2) * 132 + lr] = l;
            f2tf(w.w, h, l); sW[0][(kk + 3) * 132 + lr] = h; sW[1][(kk + 3) * 132 + lr] = l;
        }
        __syncthreads();

        #pragma unroll
        for (int ks = 0; ks < 2; ++ks) {
            const int kd = ks * 8 + t;
            uint32_t ah[2][4], al[2][4];
            #pragma unroll
            for (int m = 0; m < 2; m++) {
                const int row = wq * 32 + m * 16 + g;
                ah[m][0] = sA[0][kd * 132 + row];
                ah[m][1] = sA[0][kd * 132 + row + 8];
                ah[m][2] = sA[0][(kd + 4) * 132 + row];
                ah[m][3] = sA[0][(kd + 4) * 132 + row + 8];
                al[m][0] = sA[1][kd * 132 + row];
                al[m][1] = sA[1][kd * 132 + row + 8];
                al[m][2] = sA[1][(kd + 4) * 132 + row];
                al[m][3] = sA[1][(kd + 4) * 132 + row + 8];
            }
            #pragma unroll
            for (int nt = 0; nt < 8; ++nt) {
                const int cb = wn * 64 + nt * 8 + g;
                uint32_t bh0 = sW[0][kd * 132 + cb];
                uint32_t bh1 = sW[0][(kd + 4) * 132 + cb];
                uint32_t bl0 = sW[1][kd * 132 + cb];
                uint32_t bl1 = sW[1][(kd + 4) * 132 + cb];
                #pragma unroll
                for (int m = 0; m < 2; m++) {
                    mma8(C[m][nt], ah[m], bh0, bh1);
                    mma8(C[m][nt], ah[m], bl0, bl1);
                    mma8(C[m][nt], al[m], bh0, bh1);
                }
            }
        }
    }

    #pragma unroll
    for (int m = 0; m < 2; m++) {
        const int row0 = r0 + wq * 32 + m * 16 + g;
        #pragma unroll
        for (int nt = 0; nt < 8; ++nt) {
            const int col = c0 + wn * 64 + nt * 8 + 2 * t;
            const float b0 = bias[col], b1 = bias[col + 1];
            float v00 = C[m][nt][0] + b0, v01 = C[m][nt][1] + b1;
            float v10 = C[m][nt][2] + b0, v11 = C[m][nt][3] + b1;
            if (MODE == 0) {
                uint32_t* dH = (sel == 0) ? g_Qh : (sel == 1) ? g_Kh : g_Vh;
                uint32_t* dL = (sel == 0) ? g_Ql : (sel == 1) ? g_Kl : g_Vl;
                #pragma unroll
                for (int e = 0; e < 4; ++e) {
                    const int r = row0 + (e >> 1) * 8;
                    const int c = col + (e & 1);
                    const float v = (e == 0) ? v00 : (e == 1) ? v01 : (e == 2) ? v10 : v11;
                    const int ri = r >> 12;
                    const int bl = r & 4095;
                    const int bb = bl >> 11;
                    const int l  = bl & 2047;
                    const int h  = c >> 6;
                    const int dh = c & 63;
                    size_t pb = (((size_t)ri * QB + bb) * QH + h) * ((size_t)QL * QDh);
                    size_t idx;
                    if (sel == 0) idx = pb + qfrag_idx(l, dh);
                    else          idx = pb + (size_t)l * QDh + dh;
                    uint32_t hh, ll; f2tf(v, hh, ll);
                    dH[idx] = hh; dL[idx] = ll;
                }
            } else {
                *(float2*)(Yext + (size_t)row0 * 512 + col) = make_float2(v00, v01);
                *(float2*)(Yext + (size_t)(row0 + 8) * 512 + col) = make_float2(v10, v11);
            }
        }
    }
}

// ---------------------------------------------------------------------------
// QK on tensor cores. Block: 256 q x 64 n, 8 warps, warp tile 32q x 64n.
// A (Q) loaded as coalesced uint4 from fragment-major planes.
// Sr = QrKr + QiKi ; Si = QrKi + (-Qi)Kr.  Split-tf32, 3 passes/product.
// ---------------------------------------------------------------------------
__global__ __launch_bounds__(256) void qk_mma()
{
    __shared__ uint32_t sB[4][32 * 72];

    const int bh = blockIdx.z;
    const int q0 = blockIdx.y * 256;
    const int n0 = blockIdx.x * 64;
    const int tid = threadIdx.x;
    const int warp = tid >> 5, lane = tid & 31;
    const int g = lane >> 2, t = lane & 3;
    const int qw = q0 + warp * 32;

    const size_t hb = (size_t)bh * QL * QDh;
    const uint32_t* QrH = g_Qh + hb;
    const uint32_t* QrL = g_Ql + hb;
    const uint32_t* QiH = g_Qh + RIOFF + hb;
    const uint32_t* QiL = g_Ql + RIOFF + hb;
    const uint32_t* Ks[4] = { g_Kh + hb, g_Kl + hb,
                              g_Kh + RIOFF + hb, g_Kl + RIOFF + hb };

    float Sr[2][8][4], Si[2][8][4];
    #pragma unroll
    for (int m = 0; m < 2; m++)
        #pragma unroll
        for (int i = 0; i < 8; i++)
            #pragma unroll
            for (int j = 0; j < 4; j++) { Sr[m][i][j] = 0.f; Si[m][i][j] = 0.f; }

    #pragma unroll
    for (int kc = 0; kc < 2; ++kc) {
        __syncthreads();
        #pragma unroll
        for (int it = 0; it < 2; ++it) {
            int s = tid + it * 256;
            int n = s & 63, dg = s >> 6;
            #pragma unroll
            for (int p = 0; p < 4; p++) {
                uint4 v = *(const uint4*)(Ks[p] + (size_t)(n0 + n) * QDh + kc * 32 + dg * 4);
                sB[p][(dg * 4 + 0) * 72 + n] = v.x;
                sB[p][(dg * 4 + 1) * 72 + n] = v.y;
                sB[p][(dg * 4 + 2) * 72 + n] = v.z;
                sB[p][(dg * 4 + 3) * 72 + n] = v.w;
            }
        }
        __syncthreads();

        #pragma unroll
        for (int ks = 0; ks < 4; ++ks) {
            uint32_t qrh[2][4], qrl[2][4], qih[2][4], qil[2][4], nih[2][4], nil_[2][4];
            #pragma unroll
            for (int m = 0; m < 2; m++) {
                const uint32_t off = (uint32_t)(((qw + m * 16) >> 4) * 1024
                                     + kc * 512 + ks * 128 + t * 32 + g * 4);
                uint4 v;
                v = *(const uint4*)(QrH + off);
                qrh[m][0] = v.x; qrh[m][1] = v.y; qrh[m][2] = v.z; qrh[m][3] = v.w;
                v = *(const uint4*)(QrL + off);
                qrl[m][0] = v.x; qrl[m][1] = v.y; qrl[m][2] = v.z; qrl[m][3] = v.w;
                v = *(const uint4*)(QiH + off);
                qih[m][0] = v.x; qih[m][1] = v.y; qih[m][2] = v.z; qih[m][3] = v.w;
                v = *(const uint4*)(QiL + off);
                qil[m][0] = v.x; qil[m][1] = v.y; qil[m][2] = v.z; qil[m][3] = v.w;
                #pragma unroll
                for (int e = 0; e < 4; e++) {
                    nih[m][e]  = qih[m][e] ^ 0x80000000u;
                    nil_[m][e] = qil[m][e] ^ 0x80000000u;
                }
            }
            const int rr1 = (ks * 8 + t) * 72, rr2 = (ks * 8 + t + 4) * 72;
            #pragma unroll
            for (int nt = 0; nt < 8; ++nt) {
                const int cb = nt * 8 + g;
                uint32_t krh0 = sB[0][rr1 + cb], krh1 = sB[0][rr2 + cb];
                uint32_t krl0 = sB[1][rr1 + cb], krl1 = sB[1][rr2 + cb];
                uint32_t kih0 = sB[2][rr1 + cb], kih1 = sB[2][rr2 + cb];
                uint32_t kil0 = sB[3][rr1 + cb], kil1 = sB[3][rr2 + cb];
                #pragma unroll
                for (int m = 0; m < 2; m++) {
                    mma8(Sr[m][nt], qrh[m], krh0, krh1);
                    mma8(Sr[m][nt], qrh[m], krl0, krl1);
                    mma8(Sr[m][nt], qrl[m], krh0, krh1);
                    mma8(Sr[m][nt], qih[m], kih0, kih1);
                    mma8(Sr[m][nt], qih[m], kil0, kil1);
                    mma8(Sr[m][nt], qil[m], kih0, kih1);
                    mma8(Si[m][nt], qrh[m], kih0, kih1);
                    mma8(Si[m][nt], qrh[m], kil0, kil1);
                    mma8(Si[m][nt], qrl[m], kih0, kih1);
                    mma8(Si[m][nt], nih[m], krh0, krh1);
                    mma8(Si[m][nt], nih[m], krl0, krl1);
                    mma8(Si[m][nt], nil_[m], krh0, krh1);
                }
            }
        }
    }

    const size_t base = (size_t)bh * QL * QL;
    #pragma unroll
    for (int m = 0; m < 2; m++) {
        #pragma unroll
        for (int nt = 0; nt < 8; ++nt) {
            const int col = n0 + nt * 8 + 2 * t;
            size_t o0 = base + (size_t)(qw + m * 16 + g) * QL + col;
            size_t o1 = base + (size_t)(qw + m * 16 + g + 8) * QL + col;
            *(float2*)(g_Sr + o0) = make_float2(Sr[m][nt][0], Sr[m][nt][1]);
            *(float2*)(g_Si + o0) = make_float2(Si[m][nt][0], Si[m][nt][1]);
            *(float2*)(g_Sr + o1) = make_float2(Sr[m][nt][2], Sr[m][nt][3]);
            *(float2*)(g_Si + o1) = make_float2(Si[m][nt][2], Si[m][nt][3]);
        }
    }
}

// ---------------------------------------------------------------------------
// Fused softmax + phase (unchanged from Round 13).
// ---------------------------------------------------------------------------
__global__ __launch_bounds__(256) void phase_kernel(float* __restrict__ attn)
{
    const int row = blockIdx.x;
    float* sr = g_Sr + (size_t)row * QL;
    float* si = g_Si + (size_t)row * QL;
    float* at = attn + (size_t)row * QL;
    const int tid = threadIdx.x;

    float a[8], b[8], e[8];
    float mx = -3.4e38f;
    #pragma unroll
    for (int i = 0; i < 8; i++) {
        int k = i * 256 + tid;
        a[i] = sr[k]; b[i] = si[k];
        float s = (a[i] * a[i] + b[i] * b[i]) * 0.125f;
        e[i] = s;
        mx = fmaxf(mx, s);
    }

    __shared__ float red[256];
    red[tid] = mx;
    __syncthreads();
    #pragma unroll
    for (int off = 128; off > 0; off >>= 1) {
        if (tid < off) red[tid] = fmaxf(red[tid], red[tid + off]);
        __syncthreads();
    }
    const float m = red[0];
    __syncthreads();

    float sum = 0.f;
    #pragma unroll
    for (int i = 0; i < 8; i++) {
        e[i] = exp_neg_fast(e[i] - m);
        sum += e[i];
    }
    red[tid] = sum;
    __syncthreads();
    #pragma unroll
    for (int off = 128; off > 0; off >>= 1) {
        if (tid < off) red[tid] += red[tid + off];
        __syncthreads();
    }
    const float il = 1.0f / red[0];

    #pragma unroll
    for (int i = 0; i < 8; i++) {
        int k = i * 256 + tid;
        float A = e[i] * il;
        at[k] = A;
        float r2 = a[i] * a[i] + b[i] * b[i];
        float cr = 1.f, sn = 0.f;
        if (r2 > 0.f) {
            float inv = rsqrt_fast(r2);
            cr = a[i] * inv; sn = b[i] * inv;
        }
        sr[k] = A * cr;
        si[k] = A * sn;
    }
}

// ---------------------------------------------------------------------------
// AV on tensor cores (unchanged from Round 13).
// P single-tf32, V hi/lo; 8 MMAs per (nt,m).
// ---------------------------------------------------------------------------
__global__ __launch_bounds__(256) void av_mma()
{
    __shared__ uint32_t sV[4][32 * 72];

    const int bh = blockIdx.y;
    const int q0 = blockIdx.x * 128;
    const int tid = threadIdx.x;
    const int warp = tid >> 5, lane = tid & 31;
    const int wq = warp >> 1, wn = warp & 1;
    const int g = lane >> 2, t = lane & 3;
    const int qw = q0 + wq * 32;

    const size_t hb = (size_t)bh * QL * QDh;
    const uint32_t* Vp[4] = { g_Vh + hb, g_Vl + hb,
                              g_Vh + RIOFF + hb, g_Vl + RIOFF + hb };

    const size_t sbase = (size_t)bh * QL * QL;
    const float* Pc = g_Sr + sbase;
    const float* Ps = g_Si + sbase;

    float Or[2][4][4], Oi[2][4][4];
    #pragma unroll
    for (int m = 0; m < 2; m++)
        #pragma unroll
        for (int i = 0; i < 4; i++)
            #pragma unroll
            for (int j = 0; j < 4; j++) { Or[m][i][j] = 0.f; Oi[m][i][j] = 0.f; }

    for (int k0 = 0; k0 < QL; k0 += 32) {
        __syncthreads();
        #pragma unroll
        for (int it = 0; it < 2; ++it) {
            int idx = tid + it * 256;
            int jl = idx >> 4, dq = (idx & 15) * 4;
            #pragma unroll
            for (int p = 0; p < 4; p++) {
                uint4 v = *(const uint4*)(Vp[p] + (size_t)(k0 + jl) * QDh + dq);
                sV[p][jl * 72 + dq + 0] = v.x;
                sV[p][jl * 72 + dq + 1] = v.y;
                sV[p][jl * 72 + dq + 2] = v.z;
                sV[p][jl * 72 + dq + 3] = v.w;
            }
        }
        __syncthreads();

        #pragma unroll
        for (int ks = 0; ks < 4; ++ks) {
            uint32_t ach[2][4], ash[2][4], nsh[2][4];
            #pragma unroll
            for (int m = 0; m < 2; m++) {
                #pragma unroll
                for (int e = 0; e < 4; ++e) {
                    const int j = k0 + ks * 8 + t + (e >> 1) * 4;
                    const int row = qw + m * 16 + g + (e & 1) * 8;
                    float pc = Pc[(size_t)row * QL + j];
                    float ps = Ps[(size_t)row * QL + j];
                    ach[m][e] = tf32h(pc);
                    ash[m][e] = tf32h(ps);
                    nsh[m][e] = ash[m][e] ^ 0x80000000u;
                }
            }
            const int rr1 = (ks * 8 + t) * 72, rr2 = (ks * 8 + t + 4) * 72;
            #pragma unroll
            for (int nt = 0; nt < 4; ++nt) {
                const int cb = wn * 32 + nt * 8 + g;
                uint32_t vrh0 = sV[0][rr1 + cb], vrh1 = sV[0][rr2 + cb];
                uint32_t vrl0 = sV[1][rr1 + cb], vrl1 = sV[1][rr2 + cb];
                uint32_t vih0 = sV[2][rr1 + cb], vih1 = sV[2][rr2 + cb];
                uint32_t vil0 = sV[3][rr1 + cb], vil1 = sV[3][rr2 + cb];
                #pragma unroll
                for (int m = 0; m < 2; m++) {
                    mma8(Or[m][nt], ach[m], vrh0, vrh1);
                    mma8(Or[m][nt], ach[m], vrl0, vrl1);
                    mma8(Or[m][nt], nsh[m], vih0, vih1);
                    mma8(Or[m][nt], nsh[m], vil0, vil1);
                    mma8(Oi[m][nt], ash[m], vrh0, vrh1);
                    mma8(Oi[m][nt], ash[m], vrl0, vrl1);
                    mma8(Oi[m][nt], ach[m], vih0, vih1);
                    mma8(Oi[m][nt], ach[m], vil0, vil1);
                }
            }
        }
    }

    const int b = bh >> 3, h = bh & 7;
    #pragma unroll
    for (int m = 0; m < 2; m++) {
        const int r0 = qw + m * 16 + g, r1 = r0 + 8;
        #pragma unroll
        for (int nt = 0; nt < 4; ++nt) {
            const int dh = wn * 32 + nt * 8 + 2 * t;
            size_t o0 = ((size_t)b * QL + r0) * QD + h * QDh + dh;
            size_t o1 = ((size_t)b * QL + r1) * QD + h * QDh + dh;
            *(float2*)(g_Or + o0) = make_float2(Or[m][nt][0], Or[m][nt][1]);
            *(float2*)(g_Oi + o0) = make_float2(Oi[m][nt][0], Oi[m][nt][1]);
            *(float2*)(g_Or + o1) = make_float2(Or[m][nt][2], Or[m][nt][3]);
            *(float2*)(g_Oi + o1) = make_float2(Oi[m][nt][2], Oi[m][nt][3]);
        }
    }
}

// ---------------------------------------------------------------------------

extern "C" void kernel_launch(void* const* d_in, const int* in_sizes, int n_in,
                              void* d_out, int out_size)
{
    const float* wr = (const float*)d_in[0];
    const float* wi = (const float*)d_in[1];
    const float* Wq = (const float*)d_in[2];
    const float* bq = (const float*)d_in[3];
    const float* Wk = (const float*)d_in[4];
    const float* bk = (const float*)d_in[5];
    const float* Wv = (const float*)d_in[6];
    const float* bv = (const float*)d_in[7];
    const float* Wo = (const float*)d_in[8];
    const float* bo = (const float*)d_in[9];

    float* out      = (float*)d_out;
    float* out_real = out;
    float* out_imag = out + (size_t)QB * QL * QD;
    float* attn     = out + (size_t)2 * QB * QL * QD;

    dim3 gProj(4, 64);
    dim3 gOut(4, 32);

    proj_mma<0><<<gProj, 256>>>(wr, wi, Wq, bq, nullptr, 0);
    proj_mma<0><<<gProj, 256>>>(wr, wi, Wk, bk, nullptr, 1);
    proj_mma<0><<<gProj, 256>>>(wr, wi, Wv, bv, nullptr, 2);

    qk_mma<<<dim3(32, 8, 16), 256>>>();
    phase_kernel<<<QBH * QL, 256>>>(attn);
    av_mma<<<dim3(16, 16), 256>>>();

    proj_mma<1><<<gOut, 256>>>(nullptr, nullptr, Wo, bo, out_real, 0);
    proj_mma<1><<<gOut, 256>>>(nullptr, nullptr, Wo, bo, out_imag, 1);
}

// round 17
// speedup vs baseline: 1.6121x; 1.0831x over previous
#include <cuda_runtime.h>
#include <math.h>
#include <stdint.h>

namespace {
constexpr int QB = 2, QL = 2048, QD = 512, QH = 8, QDh = 64;
constexpr int QBH = QB * QH;
constexpr size_t RIOFF = (size_t)QBH * QL * QDh;
constexpr size_t QSZ   = 2 * RIOFF;
constexpr size_t SSZ   = (size_t)QBH * QL * QL;
}

__device__ uint32_t g_Qh[QSZ], g_Ql[QSZ];   // Q: fragment-major layout (see proj epilogue)
__device__ uint32_t g_Kh[QSZ], g_Kl[QSZ];   // K: row-major [bh][l][dh]
__device__ uint32_t g_Vh[QSZ];              // V: row-major, single tf32 (hi only)
__device__ float g_Sr[SSZ], g_Si[SSZ];      // after phase_kernel: Pc, Ps
__device__ float g_Or[(size_t)QB * QL * QD], g_Oi[(size_t)QB * QL * QD];

__device__ __forceinline__ uint32_t tf32h(float x) {
    uint32_t u; asm("cvt.rna.tf32.f32 %0, %1;" : "=r"(u) : "f"(x)); return u;
}
__device__ __forceinline__ void f2tf(float x, uint32_t& h, uint32_t& l) {
    h = tf32h(x);
    l = tf32h(x - __uint_as_float(h));
}
__device__ __forceinline__ void mma8(float c[4], const uint32_t a[4],
                                     uint32_t b0, uint32_t b1) {
    asm volatile(
        "mma.sync.aligned.m16n8k8.row.col.f32.tf32.tf32.f32 "
        "{%0,%1,%2,%3},{%4,%5,%6,%7},{%8,%9},{%0,%1,%2,%3};"
        : "+f"(c[0]), "+f"(c[1]), "+f"(c[2]), "+f"(c[3])
        : "r"(a[0]), "r"(a[1]), "r"(a[2]), "r"(a[3]), "r"(b0), "r"(b1));
}

// exp(x) for x <= 0, FMA-pipe only (no MUFU). ~1e-7 relative accuracy.
__device__ __forceinline__ float exp_neg_fast(float x) {
    const float LOG2E = 1.4426950408889634f;
    float t = x * LOG2E;
    float fl = floorf(t);
    float r = t - fl;
    float y = r * 0.6931471805599453f;
    float p = 2.4801587301587301e-5f;
    p = fmaf(p, y, 1.9841269841269841e-4f);
    p = fmaf(p, y, 1.3888888888888889e-3f);
    p = fmaf(p, y, 8.3333333333333333e-3f);
    p = fmaf(p, y, 4.1666666666666664e-2f);
    p = fmaf(p, y, 1.6666666666666666e-1f);
    p = fmaf(p, y, 5.0e-1f);
    p = fmaf(p, y, 1.0f);
    p = fmaf(p, y, 1.0f);
    int ni = (int)fl;
    ni = (ni < -127) ? -127 : ni;
    float sc = __int_as_float((uint32_t)(ni + 127) << 23);
    return p * sc;
}

__device__ __forceinline__ float rsqrt_fast(float x) {
    float y = __int_as_float(0x5f375a86u - (__float_as_uint(x) >> 1));
    y = y * fmaf(-0.5f * x, y * y, 1.5f);
    y = y * fmaf(-0.5f * x, y * y, 1.5f);
    return y;
}

// Fragment-major Q index within one bh-plane (size QL*QDh).
__device__ __forceinline__ uint32_t qfrag_idx(int l, int dh) {
    return (uint32_t)((l >> 4) * 1024 + ((dh >> 5)) * 512 + (((dh >> 3) & 3)) * 128
                      + (dh & 3) * 32 + (l & 7) * 4
                      + (((dh >> 2) & 1) * 2 + ((l >> 3) & 1)));
}

// ---------------------------------------------------------------------------
// Projections on tensor cores (split-tf32, 3 passes).
// Block 128x128, 8 warps = 4 wq x 2 wn, warp tile 32x64.
// MODE 0: scatter-store to tf32 planes: Q fragment-major hi/lo (sel 0),
//         K row-major hi/lo (sel 1), V row-major hi only (sel 2).
// MODE 1: X = g_Or/g_Oi; row-major float out.
// ---------------------------------------------------------------------------
template <int MODE>
__global__ __launch_bounds__(256) void proj_mma(
    const float* __restrict__ X0, const float* __restrict__ X1,
    const float* __restrict__ Wt, const float* __restrict__ bias,
    float* __restrict__ Yext, int sel)
{
    __shared__ uint32_t sA[2][16 * 132];
    __shared__ uint32_t sW[2][16 * 132];

    const int tid = threadIdx.x;
    const int r0 = blockIdx.y * 128;
    const int c0 = blockIdx.x * 128;

    const float* X;
    int rbase = r0;
    if (MODE == 0) {
        if (r0 >= 4096) { X = X1; rbase = r0 - 4096; }
        else            { X = X0; }
    } else {
        X = sel ? g_Oi : g_Or;
    }

    const int warp = tid >> 5, lane = tid & 31;
    const int wq = warp >> 1, wn = warp & 1;
    const int g = lane >> 2, t = lane & 3;

    const int lr = tid >> 1;
    const int lc0 = (tid & 1) << 2;

    float C[2][8][4];
    #pragma unroll
    for (int m = 0; m < 2; m++)
        #pragma unroll
        for (int i = 0; i < 8; i++)
            #pragma unroll
            for (int j = 0; j < 4; j++) C[m][i][j] = 0.f;

    for (int k0 = 0; k0 < 512; k0 += 16) {
        __syncthreads();
        #pragma unroll
        for (int it = 0; it < 2; ++it) {
            const int kk = lc0 + it * 8;
            float4 a = *(const float4*)(X  + (size_t)(rbase + lr) * 512 + k0 + kk);
            float4 w = *(const float4*)(Wt + (size_t)(c0 + lr) * 512 + k0 + kk);
            uint32_t h, l;
            f2tf(a.x, h, l); sA[0][(kk + 0) * 132 + lr] = h; sA[1][(kk + 0) * 132 + lr] = l;
            f2tf(a.y, h, l); sA[0][(kk + 1) * 132 + lr] = h; sA[1][(kk + 1) * 132 + lr] = l;
            f2tf(a.z, h, l); sA[0][(kk + 2) * 132 + lr] = h; sA[1][(kk + 2) * 132 + lr] = l;
            f2tf(a.w, h, l); sA[0][(kk + 3) * 132 + lr] = h; sA[1][(kk + 3) * 132 + lr] = l;
            f2tf(w.x, h, l); sW[0][(kk + 0) * 132 + lr] = h; sW[1][(kk + 0) * 132 + lr] = l;
            f2tf(w.y, h, l); sW[0][(kk + 1) * 132 + lr] = h; sW[1][(kk + 1) * 132 + lr] = l;
            f2tf(w.z, h, l); sW[0][(kk + 2) * 132 + lr] = h; sW[1][(kk + 2) * 132 + lr] = l;
            f2tf(w.w, h, l); sW[0][(kk + 3) * 132 + lr] = h; sW[1][(kk + 3) * 132 + lr] = l;
        }
        __syncthreads();

        #pragma unroll
        for (int ks = 0; ks < 2; ++ks) {
            const int kd = ks * 8 + t;
            uint32_t ah[2][4], al[2][4];
            #pragma unroll
            for (int m = 0; m < 2; m++) {
                const int row = wq * 32 + m * 16 + g;
                ah[m][0] = sA[0][kd * 132 + row];
                ah[m][1] = sA[0][kd * 132 + row + 8];
                ah[m][2] = sA[0][(kd + 4) * 132 + row];
                ah[m][3] = sA[0][(kd + 4) * 132 + row + 8];
                al[m][0] = sA[1][kd * 132 + row];
                al[m][1] = sA[1][kd * 132 + row + 8];
                al[m][2] = sA[1][(kd + 4) * 132 + row];
                al[m][3] = sA[1][(kd + 4) * 132 + row + 8];
            }
            #pragma unroll
            for (int nt = 0; nt < 8; ++nt) {
                const int cb = wn * 64 + nt * 8 + g;
                uint32_t bh0 = sW[0][kd * 132 + cb];
                uint32_t bh1 = sW[0][(kd + 4) * 132 + cb];
                uint32_t bl0 = sW[1][kd * 132 + cb];
                uint32_t bl1 = sW[1][(kd + 4) * 132 + cb];
                #pragma unroll
                for (int m = 0; m < 2; m++) {
                    mma8(C[m][nt], ah[m], bh0, bh1);
                    mma8(C[m][nt], ah[m], bl0, bl1);
                    mma8(C[m][nt], al[m], bh0, bh1);
                }
            }
        }
    }

    #pragma unroll
    for (int m = 0; m < 2; m++) {
        const int row0 = r0 + wq * 32 + m * 16 + g;
        #pragma unroll
        for (int nt = 0; nt < 8; ++nt) {
            const int col = c0 + wn * 64 + nt * 8 + 2 * t;
            const float b0 = bias[col], b1 = bias[col + 1];
            float v00 = C[m][nt][0] + b0, v01 = C[m][nt][1] + b1;
            float v10 = C[m][nt][2] + b0, v11 = C[m][nt][3] + b1;
            if (MODE == 0) {
                #pragma unroll
                for (int e = 0; e < 4; ++e) {
                    const int r = row0 + (e >> 1) * 8;
                    const int c = col + (e & 1);
                    const float v = (e == 0) ? v00 : (e == 1) ? v01 : (e == 2) ? v10 : v11;
                    const int ri = r >> 12;
                    const int bl = r & 4095;
                    const int bb = bl >> 11;
                    const int l  = bl & 2047;
                    const int h  = c >> 6;
                    const int dh = c & 63;
                    size_t pb = (((size_t)ri * QB + bb) * QH + h) * ((size_t)QL * QDh);
                    if (sel == 0) {
                        size_t idx = pb + qfrag_idx(l, dh);
                        uint32_t hh, ll; f2tf(v, hh, ll);
                        g_Qh[idx] = hh; g_Ql[idx] = ll;
                    } else if (sel == 1) {
                        size_t idx = pb + (size_t)l * QDh + dh;
                        uint32_t hh, ll; f2tf(v, hh, ll);
                        g_Kh[idx] = hh; g_Kl[idx] = ll;
                    } else {
                        size_t idx = pb + (size_t)l * QDh + dh;
                        g_Vh[idx] = tf32h(v);
                    }
                }
            } else {
                *(float2*)(Yext + (size_t)row0 * 512 + col) = make_float2(v00, v01);
                *(float2*)(Yext + (size_t)(row0 + 8) * 512 + col) = make_float2(v10, v11);
            }
        }
    }
}

// ---------------------------------------------------------------------------
// QK on tensor cores (unchanged from Round 14).
// ---------------------------------------------------------------------------
__global__ __launch_bounds__(256) void qk_mma()
{
    __shared__ uint32_t sB[4][32 * 72];

    const int bh = blockIdx.z;
    const int q0 = blockIdx.y * 256;
    const int n0 = blockIdx.x * 64;
    const int tid = threadIdx.x;
    const int warp = tid >> 5, lane = tid & 31;
    const int g = lane >> 2, t = lane & 3;
    const int qw = q0 + warp * 32;

    const size_t hb = (size_t)bh * QL * QDh;
    const uint32_t* QrH = g_Qh + hb;
    const uint32_t* QrL = g_Ql + hb;
    const uint32_t* QiH = g_Qh + RIOFF + hb;
    const uint32_t* QiL = g_Ql + RIOFF + hb;
    const uint32_t* Ks[4] = { g_Kh + hb, g_Kl + hb,
                              g_Kh + RIOFF + hb, g_Kl + RIOFF + hb };

    float Sr[2][8][4], Si[2][8][4];
    #pragma unroll
    for (int m = 0; m < 2; m++)
        #pragma unroll
        for (int i = 0; i < 8; i++)
            #pragma unroll
            for (int j = 0; j < 4; j++) { Sr[m][i][j] = 0.f; Si[m][i][j] = 0.f; }

    #pragma unroll
    for (int kc = 0; kc < 2; ++kc) {
        __syncthreads();
        #pragma unroll
        for (int it = 0; it < 2; ++it) {
            int s = tid + it * 256;
            int n = s & 63, dg = s >> 6;
            #pragma unroll
            for (int p = 0; p < 4; p++) {
                uint4 v = *(const uint4*)(Ks[p] + (size_t)(n0 + n) * QDh + kc * 32 + dg * 4);
                sB[p][(dg * 4 + 0) * 72 + n] = v.x;
                sB[p][(dg * 4 + 1) * 72 + n] = v.y;
                sB[p][(dg * 4 + 2) * 72 + n] = v.z;
                sB[p][(dg * 4 + 3) * 72 + n] = v.w;
            }
        }
        __syncthreads();

        #pragma unroll
        for (int ks = 0; ks < 4; ++ks) {
            uint32_t qrh[2][4], qrl[2][4], qih[2][4], qil[2][4], nih[2][4], nil_[2][4];
            #pragma unroll
            for (int m = 0; m < 2; m++) {
                const uint32_t off = (uint32_t)(((qw + m * 16) >> 4) * 1024
                                     + kc * 512 + ks * 128 + t * 32 + g * 4);
                uint4 v;
                v = *(const uint4*)(QrH + off);
                qrh[m][0] = v.x; qrh[m][1] = v.y; qrh[m][2] = v.z; qrh[m][3] = v.w;
                v = *(const uint4*)(QrL + off);
                qrl[m][0] = v.x; qrl[m][1] = v.y; qrl[m][2] = v.z; qrl[m][3] = v.w;
                v = *(const uint4*)(QiH + off);
                qih[m][0] = v.x; qih[m][1] = v.y; qih[m][2] = v.z; qih[m][3] = v.w;
                v = *(const uint4*)(QiL + off);
                qil[m][0] = v.x; qil[m][1] = v.y; qil[m][2] = v.z; qil[m][3] = v.w;
                #pragma unroll
                for (int e = 0; e < 4; e++) {
                    nih[m][e]  = qih[m][e] ^ 0x80000000u;
                    nil_[m][e] = qil[m][e] ^ 0x80000000u;
                }
            }
            const int rr1 = (ks * 8 + t) * 72, rr2 = (ks * 8 + t + 4) * 72;
            #pragma unroll
            for (int nt = 0; nt < 8; ++nt) {
                const int cb = nt * 8 + g;
                uint32_t krh0 = sB[0][rr1 + cb], krh1 = sB[0][rr2 + cb];
                uint32_t krl0 = sB[1][rr1 + cb], krl1 = sB[1][rr2 + cb];
                uint32_t kih0 = sB[2][rr1 + cb], kih1 = sB[2][rr2 + cb];
                uint32_t kil0 = sB[3][rr1 + cb], kil1 = sB[3][rr2 + cb];
                #pragma unroll
                for (int m = 0; m < 2; m++) {
                    mma8(Sr[m][nt], qrh[m], krh0, krh1);
                    mma8(Sr[m][nt], qrh[m], krl0, krl1);
                    mma8(Sr[m][nt], qrl[m], krh0, krh1);
                    mma8(Sr[m][nt], qih[m], kih0, kih1);
                    mma8(Sr[m][nt], qih[m], kil0, kil1);
                    mma8(Sr[m][nt], qil[m], kih0, kih1);
                    mma8(Si[m][nt], qrh[m], kih0, kih1);
                    mma8(Si[m][nt], qrh[m], kil0, kil1);
                    mma8(Si[m][nt], qrl[m], kih0, kih1);
                    mma8(Si[m][nt], nih[m], krh0, krh1);
                    mma8(Si[m][nt], nih[m], krl0, krl1);
                    mma8(Si[m][nt], nil_[m], krh0, krh1);
                }
            }
        }
    }

    const size_t base = (size_t)bh * QL * QL;
    #pragma unroll
    for (int m = 0; m < 2; m++) {
        #pragma unroll
        for (int nt = 0; nt < 8; ++nt) {
            const int col = n0 + nt * 8 + 2 * t;
            size_t o0 = base + (size_t)(qw + m * 16 + g) * QL + col;
            size_t o1 = base + (size_t)(qw + m * 16 + g + 8) * QL + col;
            *(float2*)(g_Sr + o0) = make_float2(Sr[m][nt][0], Sr[m][nt][1]);
            *(float2*)(g_Si + o0) = make_float2(Si[m][nt][0], Si[m][nt][1]);
            *(float2*)(g_Sr + o1) = make_float2(Sr[m][nt][2], Sr[m][nt][3]);
            *(float2*)(g_Si + o1) = make_float2(Si[m][nt][2], Si[m][nt][3]);
        }
    }
}

// ---------------------------------------------------------------------------
// Fused softmax + phase (unchanged).
// ---------------------------------------------------------------------------
__global__ __launch_bounds__(256) void phase_kernel(float* __restrict__ attn)
{
    const int row = blockIdx.x;
    float* sr = g_Sr + (size_t)row * QL;
    float* si = g_Si + (size_t)row * QL;
    float* at = attn + (size_t)row * QL;
    const int tid = threadIdx.x;

    float a[8], b[8], e[8];
    float mx = -3.4e38f;
    #pragma unroll
    for (int i = 0; i < 8; i++) {
        int k = i * 256 + tid;
        a[i] = sr[k]; b[i] = si[k];
        float s = (a[i] * a[i] + b[i] * b[i]) * 0.125f;
        e[i] = s;
        mx = fmaxf(mx, s);
    }

    __shared__ float red[256];
    red[tid] = mx;
    __syncthreads();
    #pragma unroll
    for (int off = 128; off > 0; off >>= 1) {
        if (tid < off) red[tid] = fmaxf(red[tid], red[tid + off]);
        __syncthreads();
    }
    const float m = red[0];
    __syncthreads();

    float sum = 0.f;
    #pragma unroll
    for (int i = 0; i < 8; i++) {
        e[i] = exp_neg_fast(e[i] - m);
        sum += e[i];
    }
    red[tid] = sum;
    __syncthreads();
    #pragma unroll
    for (int off = 128; off > 0; off >>= 1) {
        if (tid < off) red[tid] += red[tid + off];
        __syncthreads();
    }
    const float il = 1.0f / red[0];

    #pragma unroll
    for (int i = 0; i < 8; i++) {
        int k = i * 256 + tid;
        float A = e[i] * il;
        at[k] = A;
        float r2 = a[i] * a[i] + b[i] * b[i];
        float cr = 1.f, sn = 0.f;
        if (r2 > 0.f) {
            float inv = rsqrt_fast(r2);
            cr = a[i] * inv; sn = b[i] * inv;
        }
        sr[k] = A * cr;
        si[k] = A * sn;
    }
}

// ---------------------------------------------------------------------------
// AV on tensor cores. P single-tf32 (R13), V single-tf32 (new):
// 4 MMAs per (nt,m).  Or = Pc*Vr + (-Ps)*Vi ; Oi = Ps*Vr + Pc*Vi.
// Block: 128 q x Dh=64; 8 warps = 4 wq (32q, 2 m-tiles) x 2 wn (32dh).
// ---------------------------------------------------------------------------
__global__ __launch_bounds__(256) void av_mma()
{
    __shared__ uint32_t sV[2][32 * 72];   // VrH, ViH  [j][dh] pitch 72

    const int bh = blockIdx.y;
    const int q0 = blockIdx.x * 128;
    const int tid = threadIdx.x;
    const int warp = tid >> 5, lane = tid & 31;
    const int wq = warp >> 1, wn = warp & 1;
    const int g = lane >> 2, t = lane & 3;
    const int qw = q0 + wq * 32;

    const size_t hb = (size_t)bh * QL * QDh;
    const uint32_t* Vp[2] = { g_Vh + hb, g_Vh + RIOFF + hb };

    const size_t sbase = (size_t)bh * QL * QL;
    const float* Pc = g_Sr + sbase;
    const float* Ps = g_Si + sbase;

    float Or[2][4][4], Oi[2][4][4];
    #pragma unroll
    for (int m = 0; m < 2; m++)
        #pragma unroll
        for (int i = 0; i < 4; i++)
            #pragma unroll
            for (int j = 0; j < 4; j++) { Or[m][i][j] = 0.f; Oi[m][i][j] = 0.f; }

    for (int k0 = 0; k0 < QL; k0 += 32) {
        __syncthreads();
        #pragma unroll
        for (int it = 0; it < 2; ++it) {
            int idx = tid + it * 256;
            int jl = idx >> 4, dq = (idx & 15) * 4;
            #pragma unroll
            for (int p = 0; p < 2; p++) {
                uint4 v = *(const uint4*)(Vp[p] + (size_t)(k0 + jl) * QDh + dq);
                sV[p][jl * 72 + dq + 0] = v.x;
                sV[p][jl * 72 + dq + 1] = v.y;
                sV[p][jl * 72 + dq + 2] = v.z;
                sV[p][jl * 72 + dq + 3] = v.w;
            }
        }
        __syncthreads();

        #pragma unroll
        for (int ks = 0; ks < 4; ++ks) {
            uint32_t ach[2][4], ash[2][4], nsh[2][4];
            #pragma unroll
            for (int m = 0; m < 2; m++) {
                #pragma unroll
                for (int e = 0; e < 4; ++e) {
                    const int j = k0 + ks * 8 + t + (e >> 1) * 4;
                    const int row = qw + m * 16 + g + (e & 1) * 8;
                    float pc = Pc[(size_t)row * QL + j];
                    float ps = Ps[(size_t)row * QL + j];
                    ach[m][e] = tf32h(pc);
                    ash[m][e] = tf32h(ps);
                    nsh[m][e] = ash[m][e] ^ 0x80000000u;
                }
            }
            const int rr1 = (ks * 8 + t) * 72, rr2 = (ks * 8 + t + 4) * 72;
            #pragma unroll
            for (int nt = 0; nt < 4; ++nt) {
                const int cb = wn * 32 + nt * 8 + g;
                uint32_t vr0 = sV[0][rr1 + cb], vr1 = sV[0][rr2 + cb];
                uint32_t vi0 = sV[1][rr1 + cb], vi1 = sV[1][rr2 + cb];
                #pragma unroll
                for (int m = 0; m < 2; m++) {
                    mma8(Or[m][nt], ach[m], vr0, vr1);
                    mma8(Or[m][nt], nsh[m], vi0, vi1);
                    mma8(Oi[m][nt], ash[m], vr0, vr1);
                    mma8(Oi[m][nt], ach[m], vi0, vi1);
                }
            }
        }
    }

    const int b = bh >> 3, h = bh & 7;
    #pragma unroll
    for (int m = 0; m < 2; m++) {
        const int r0 = qw + m * 16 + g, r1 = r0 + 8;
        #pragma unroll
        for (int nt = 0; nt < 4; ++nt) {
            const int dh = wn * 32 + nt * 8 + 2 * t;
            size_t o0 = ((size_t)b * QL + r0) * QD + h * QDh + dh;
            size_t o1 = ((size_t)b * QL + r1) * QD + h * QDh + dh;
            *(float2*)(g_Or + o0) = make_float2(Or[m][nt][0], Or[m][nt][1]);
            *(float2*)(g_Oi + o0) = make_float2(Oi[m][nt][0], Oi[m][nt][1]);
            *(float2*)(g_Or + o1) = make_float2(Or[m][nt][2], Or[m][nt][3]);
            *(float2*)(g_Oi + o1) = make_float2(Oi[m][nt][2], Oi[m][nt][3]);
        }
    }
}

// ---------------------------------------------------------------------------

extern "C" void kernel_launch(void* const* d_in, const int* in_sizes, int n_in,
                              void* d_out, int out_size)
{
    const float* wr = (const float*)d_in[0];
    const float* wi = (const float*)d_in[1];
    const float* Wq = (const float*)d_in[2];
    const float* bq = (const float*)d_in[3];
    const float* Wk = (const float*)d_in[4];
    const float* bk = (const float*)d_in[5];
    const float* Wv = (const float*)d_in[6];
    const float* bv = (const float*)d_in[7];
    const float* Wo = (const float*)d_in[8];
    const float* bo = (const float*)d_in[9];

    float* out      = (float*)d_out;
    float* out_real = out;
    float* out_imag = out + (size_t)QB * QL * QD;
    float* attn     = out + (size_t)2 * QB * QL * QD;

    dim3 gProj(4, 64);
    dim3 gOut(4, 32);

    proj_mma<0><<<gProj, 256>>>(wr, wi, Wq, bq, nullptr, 0);
    proj_mma<0><<<gProj, 256>>>(wr, wi, Wk, bk, nullptr, 1);
    proj_mma<0><<<gProj, 256>>>(wr, wi, Wv, bv, nullptr, 2);

    qk_mma<<<dim3(32, 8, 16), 256>>>();
    phase_kernel<<<QBH * QL, 256>>>(attn);
    av_mma<<<dim3(16, 16), 256>>>();

    proj_mma<1><<<gOut, 256>>>(nullptr, nullptr, Wo, bo, out_real, 0);
    proj_mma<1><<<gOut, 256>>>(nullptr, nullptr, Wo, bo, out_imag, 1);
}